// round 4
// baseline (speedup 1.0000x reference)
#include <cuda_runtime.h>
#include <cuda_bf16.h>
#include <cstdint>

#define NN 100000
#define DD 128

// Scratch (static device globals — allocation-free at runtime)
__device__ float g_agg[NN * DD];           // 51.2 MB edge-sum accumulator
__device__ float g_deg[NN];                // in-degree (float)
__device__ __nv_bfloat16 g_Whi[DD * DD];   // W split high (row-major [n][k])
__device__ __nv_bfloat16 g_Wlo[DD * DD];   // W split low
__device__ int g_is64;                     // 1 if src/dst are int64

// ---------------------------------------------------------------------------
// Index dtype detection (int64 vs int32): int64 values < 2^31 have all-zero
// odd 32-bit words; int32 node ids over 512 samples cannot.
// ---------------------------------------------------------------------------
__global__ void detect_dtype_kernel(const unsigned int* __restrict__ src) {
    if (threadIdx.x == 0 && blockIdx.x == 0) {
        unsigned int acc = 0;
        #pragma unroll 8
        for (int i = 0; i < 512; ++i) acc |= src[2 * i + 1];
        g_is64 = (acc == 0u) ? 1 : 0;
    }
}

__global__ void zero_kernel() {
    int i = blockIdx.x * blockDim.x + threadIdx.x;
    float4 z = make_float4(0.f, 0.f, 0.f, 0.f);
    if (i < NN * DD / 4) reinterpret_cast<float4*>(g_agg)[i] = z;
    if (i < NN / 4)      reinterpret_cast<float4*>(g_deg)[i] = z;
}

// Split W into bf16 hi/lo (Markidis): W ~= hi + lo to ~16 mantissa bits.
__global__ void wprep_kernel(const float* __restrict__ W) {
    int i = blockIdx.x * blockDim.x + threadIdx.x;
    if (i < DD * DD) {
        float w = W[i];
        __nv_bfloat16 hi = __float2bfloat16(w);
        g_Whi[i] = hi;
        g_Wlo[i] = __float2bfloat16(w - __bfloat162float(hi));
    }
}

// ---------------------------------------------------------------------------
// Edge scatter: 4 edges per warp, 8 lanes per edge, 4 float4 per lane.
// At the LTS cap (~10.3 TB/s effective) — unchanged from R3.
// ---------------------------------------------------------------------------
__global__ void scatter_kernel(const void* __restrict__ srcv,
                               const void* __restrict__ dstv,
                               const float4* __restrict__ feat4, int nE) {
    int gid = blockIdx.x * blockDim.x + threadIdx.x;
    int warp = gid >> 5, lane = gid & 31;
    int e = warp * 4 + (lane >> 3);
    if (e >= nE) return;
    int li = lane & 7;

    long long s, d;
    if (g_is64) {
        s = reinterpret_cast<const long long*>(srcv)[e];
        d = reinterpret_cast<const long long*>(dstv)[e];
    } else {
        s = reinterpret_cast<const int*>(srcv)[e];
        d = reinterpret_cast<const int*>(dstv)[e];
    }

    float4 v[4];
    #pragma unroll
    for (int j = 0; j < 4; j++) v[j] = feat4[s * 32 + li + j * 8];
    #pragma unroll
    for (int j = 0; j < 4; j++) {
        float* p = &g_agg[d * DD + (li + j * 8) * 4];
        asm volatile("red.global.add.v4.f32 [%0], {%1,%2,%3,%4};"
                     :: "l"(p), "f"(v[j].x), "f"(v[j].y), "f"(v[j].z), "f"(v[j].w)
                     : "memory");
    }
    if (li == 0) atomicAdd(&g_deg[d], 1.0f);
}

// ---------------------------------------------------------------------------
// Split-bf16 GEMM via mma.sync.m16n8k16:
//   out[m] = (agg[m] * inv_deg[m]) @ W^T + b
//   acc = Ahi*Bhi + Ahi*Blo + Alo*Bhi (fp32 acc; lo*lo dropped, ~2^-18)
// B (hi/lo) staged in smem with 272 B row stride (8-row ldmatrix phases hit
// all 32 banks). A fragments load direct from L2 as float2, split on the fly;
// Ahi cached in regs, Alo recomputed in pass 2. 70 KB smem -> 2 CTAs/SM.
// ---------------------------------------------------------------------------
#define ROWB   272                       // bytes per smem B row (136 bf16)
#define SB_HI  0
#define SB_LO  34816
#define SM_TOTAL (2 * 34816)

__device__ __forceinline__ uint32_t smem_u32(const void* p) {
    uint32_t a;
    asm("{ .reg .u64 t; cvta.to.shared.u64 t, %1; cvt.u32.u64 %0, t; }"
        : "=r"(a) : "l"(p));
    return a;
}
__device__ __forceinline__ void mma16816(float* c, uint32_t a0, uint32_t a1,
                                         uint32_t a2, uint32_t a3,
                                         uint32_t b0, uint32_t b1) {
    asm volatile(
        "mma.sync.aligned.m16n8k16.row.col.f32.bf16.bf16.f32 "
        "{%0,%1,%2,%3}, {%4,%5,%6,%7}, {%8,%9}, {%0,%1,%2,%3};"
        : "+f"(c[0]), "+f"(c[1]), "+f"(c[2]), "+f"(c[3])
        : "r"(a0), "r"(a1), "r"(a2), "r"(a3), "r"(b0), "r"(b1));
}
__device__ __forceinline__ void ldsm4(uint32_t& r0, uint32_t& r1,
                                      uint32_t& r2, uint32_t& r3, uint32_t a) {
    asm volatile("ldmatrix.sync.aligned.m8n8.x4.shared.b16 {%0,%1,%2,%3}, [%4];"
                 : "=r"(r0), "=r"(r1), "=r"(r2), "=r"(r3) : "r"(a));
}
// pack two floats to bf16x2: lo half = x, hi half = y (k ascending)
__device__ __forceinline__ uint32_t packbf(float y, float x) {
    uint32_t r;
    asm("cvt.rn.bf16x2.f32 %0, %1, %2;" : "=r"(r) : "f"(y), "f"(x));
    return r;
}
__device__ __forceinline__ float bf_lo(uint32_t u) { return __uint_as_float(u << 16); }
__device__ __forceinline__ float bf_hi(uint32_t u) { return __uint_as_float(u & 0xFFFF0000u); }

__global__ __launch_bounds__(256, 2) void gcn_mma_kernel(
    const float* __restrict__ bias, float* __restrict__ out, int nrows) {
    extern __shared__ char smem[];
    const int t = threadIdx.x, wid = t >> 5, lane = t & 31;
    const int q = lane >> 2, s = lane & 3;
    const int rowbase = blockIdx.x * 128 + wid * 16;   // warp owns 16 rows

    // ---- Stage B hi/lo into strided smem (packed bf16x2 stores) ----
    const uint32_t* whi = reinterpret_cast<const uint32_t*>(g_Whi);
    const uint32_t* wlo = reinterpret_cast<const uint32_t*>(g_Wlo);
    #pragma unroll
    for (int i = 0; i < 32; i++) {
        int p = t + i * 256;                 // p = n*64 + kp
        int n = p >> 6, kp = p & 63;
        uint32_t off = n * ROWB + kp * 4;
        *reinterpret_cast<uint32_t*>(smem + SB_HI + off) = whi[p];
        *reinterpret_cast<uint32_t*>(smem + SB_LO + off) = wlo[p];
    }

    // ---- A prologue: direct L2 loads, split hi into regs ----
    const int r0 = rowbase + q, r1 = rowbase + q + 8;
    const bool p0 = r0 < nrows, p1 = r1 < nrows;
    const float* A0 = &g_agg[(size_t)r0 * DD + s * 2];
    const float* A1 = &g_agg[(size_t)r1 * DD + s * 2];
    const float2 zz = make_float2(0.f, 0.f);

    uint32_t Ahi[8][4];
    #pragma unroll
    for (int ks = 0; ks < 8; ks++) {
        int k = ks * 16;
        float2 v0 = p0 ? *reinterpret_cast<const float2*>(A0 + k)     : zz;
        float2 v1 = p1 ? *reinterpret_cast<const float2*>(A1 + k)     : zz;
        float2 v2 = p0 ? *reinterpret_cast<const float2*>(A0 + k + 8) : zz;
        float2 v3 = p1 ? *reinterpret_cast<const float2*>(A1 + k + 8) : zz;
        Ahi[ks][0] = packbf(v0.y, v0.x);
        Ahi[ks][1] = packbf(v1.y, v1.x);
        Ahi[ks][2] = packbf(v2.y, v2.x);
        Ahi[ks][3] = packbf(v3.y, v3.x);
    }
    __syncthreads();

    // ldmatrix lane pointer part: matrices {n0..7@k0, n0..7@k0+8, n8..15@k0, n8..15@k0+8}
    const uint32_t sbase = smem_u32(smem);
    const uint32_t lanep = (((lane & 16) >> 1) + (lane & 7)) * ROWB
                         + ((lane >> 3) & 1) * 16;
    const uint32_t bhi_l = sbase + SB_HI + lanep;
    const uint32_t blo_l = sbase + SB_LO + lanep;

    float acc[16][4];
    #pragma unroll
    for (int nt = 0; nt < 16; nt++)
        #pragma unroll
        for (int c = 0; c < 4; c++) acc[nt][c] = 0.f;

    #pragma unroll
    for (int pass = 0; pass < 3; pass++) {
        const uint32_t bb = (pass == 1) ? blo_l : bhi_l;
        #pragma unroll
        for (int ks = 0; ks < 8; ks++) {
            uint32_t a0, a1, a2, a3;
            if (pass < 2) {
                a0 = Ahi[ks][0]; a1 = Ahi[ks][1];
                a2 = Ahi[ks][2]; a3 = Ahi[ks][3];
            } else {
                int k = ks * 16;
                float2 v0 = p0 ? *reinterpret_cast<const float2*>(A0 + k)     : zz;
                float2 v1 = p1 ? *reinterpret_cast<const float2*>(A1 + k)     : zz;
                float2 v2 = p0 ? *reinterpret_cast<const float2*>(A0 + k + 8) : zz;
                float2 v3 = p1 ? *reinterpret_cast<const float2*>(A1 + k + 8) : zz;
                a0 = packbf(v0.y - bf_hi(Ahi[ks][0]), v0.x - bf_lo(Ahi[ks][0]));
                a1 = packbf(v1.y - bf_hi(Ahi[ks][1]), v1.x - bf_lo(Ahi[ks][1]));
                a2 = packbf(v2.y - bf_hi(Ahi[ks][2]), v2.x - bf_lo(Ahi[ks][2]));
                a3 = packbf(v3.y - bf_hi(Ahi[ks][3]), v3.x - bf_lo(Ahi[ks][3]));
            }
            #pragma unroll
            for (int np = 0; np < 8; np++) {
                uint32_t b0, b1, b2, b3;
                ldsm4(b0, b1, b2, b3, bb + np * (16 * ROWB) + ks * 32);
                mma16816(acc[np * 2],     a0, a1, a2, a3, b0, b1);
                mma16816(acc[np * 2 + 1], a0, a1, a2, a3, b2, b3);
            }
        }
    }

    // ---- Epilogue: out[m][n] = acc * inv_deg[m] + bias[n] ----
    float dgA = p0 ? g_deg[r0] : 0.f;
    float dgB = p1 ? g_deg[r1] : 0.f;
    float invA = (dgA > 0.f) ? (1.f / dgA) : 0.f;
    float invB = (dgB > 0.f) ? (1.f / dgB) : 0.f;
    #pragma unroll
    for (int nt = 0; nt < 16; nt++) {
        int n = nt * 8 + s * 2;
        float2 bv = *reinterpret_cast<const float2*>(&bias[n]);
        if (p0) {
            float2 o = make_float2(acc[nt][0] * invA + bv.x,
                                   acc[nt][1] * invA + bv.y);
            *reinterpret_cast<float2*>(&out[(size_t)r0 * DD + n]) = o;
        }
        if (p1) {
            float2 o = make_float2(acc[nt][2] * invB + bv.x,
                                   acc[nt][3] * invB + bv.y);
            *reinterpret_cast<float2*>(&out[(size_t)r1 * DD + n]) = o;
        }
    }
}

extern "C" void kernel_launch(void* const* d_in, const int* in_sizes, int n_in,
                              void* d_out, int out_size) {
    const float* feature = (const float*)d_in[0];   // [100000,128] f32
    const float* W       = (const float*)d_in[1];   // [128,128]   f32
    const float* bias    = (const float*)d_in[2];   // [128]       f32
    const void*  src     = d_in[3];                 // [625000] int64/int32
    const void*  dst     = d_in[4];                 // [625000] int64/int32
    float*       out     = (float*)d_out;           // [100000,128] f32

    const int nE = in_sizes[3];
    const int nN = in_sizes[0] / DD;

    detect_dtype_kernel<<<1, 32>>>((const unsigned int*)src);

    int zero_threads = NN * DD / 4;
    zero_kernel<<<(zero_threads + 255) / 256, 256>>>();

    wprep_kernel<<<(DD * DD + 255) / 256, 256>>>(W);

    long long scatter_threads = (long long)nE * 8;   // 8 lanes per edge
    scatter_kernel<<<(unsigned)((scatter_threads + 255) / 256), 256>>>(
        src, dst, (const float4*)feature, nE);

    cudaFuncSetAttribute(gcn_mma_kernel,
                         cudaFuncAttributeMaxDynamicSharedMemorySize, SM_TOTAL);
    gcn_mma_kernel<<<(nN + 127) / 128, 256, SM_TOTAL>>>(bias, out, nN);
}

// round 5
// speedup vs baseline: 1.2199x; 1.2199x over previous
#include <cuda_runtime.h>
#include <cuda_fp16.h>
#include <cstdint>

#define NN 100000
#define DD 128
#define STRB 72      // 32-bit words per smem B row (72 mod 32 = 8 -> conflict-free)

// Scratch (static device globals — allocation-free at runtime)
__device__ float g_agg[NN * DD];   // 51.2 MB edge-sum accumulator
__device__ float g_deg[NN];        // in-degree (float)
__device__ int   g_is64;           // 1 if src/dst are int64

// ---------------------------------------------------------------------------
// Fused prep: zero agg+deg, and detect index dtype (int64 values < 2^31 have
// all-zero odd 32-bit words; int32 node ids over 512 samples cannot).
// ---------------------------------------------------------------------------
__global__ void prep_kernel(const unsigned int* __restrict__ src) {
    int i = blockIdx.x * blockDim.x + threadIdx.x;
    float4 z = make_float4(0.f, 0.f, 0.f, 0.f);
    if (i < NN * DD / 4) reinterpret_cast<float4*>(g_agg)[i] = z;
    if (i < NN / 4)      reinterpret_cast<float4*>(g_deg)[i] = z;
    if (i == 0) {
        unsigned int acc = 0;
        #pragma unroll 8
        for (int j = 0; j < 512; ++j) acc |= src[2 * j + 1];
        g_is64 = (acc == 0u) ? 1 : 0;
    }
}

// ---------------------------------------------------------------------------
// Edge scatter: 4 edges per warp, 8 lanes per edge, 4 float4 per lane.
// At the LTS cap (~10 TB/s effective L2) — unchanged.
// ---------------------------------------------------------------------------
__global__ void scatter_kernel(const void* __restrict__ srcv,
                               const void* __restrict__ dstv,
                               const float4* __restrict__ feat4, int nE) {
    int gid = blockIdx.x * blockDim.x + threadIdx.x;
    int warp = gid >> 5, lane = gid & 31;
    int e = warp * 4 + (lane >> 3);
    if (e >= nE) return;
    int li = lane & 7;

    long long s, d;
    if (g_is64) {
        s = reinterpret_cast<const long long*>(srcv)[e];
        d = reinterpret_cast<const long long*>(dstv)[e];
    } else {
        s = reinterpret_cast<const int*>(srcv)[e];
        d = reinterpret_cast<const int*>(dstv)[e];
    }

    float4 v[4];
    #pragma unroll
    for (int j = 0; j < 4; j++) v[j] = feat4[s * 32 + li + j * 8];
    #pragma unroll
    for (int j = 0; j < 4; j++) {
        float* p = &g_agg[d * DD + (li + j * 8) * 4];
        asm volatile("red.global.add.v4.f32 [%0], {%1,%2,%3,%4};"
                     :: "l"(p), "f"(v[j].x), "f"(v[j].y), "f"(v[j].z), "f"(v[j].w)
                     : "memory");
    }
    if (li == 0) atomicAdd(&g_deg[d], 1.0f);
}

// ---------------------------------------------------------------------------
// Single-pass fp16 GEMM via mma.sync.m16n8k16.f32.f16.f16.f32:
//   out[m] = (agg[m] * inv_deg[m]) @ W^T + b
// fp16 has 11 significand bits -> ~3e-4 output rel err (fp32 accumulate).
// B = W[n][k] converted to f16x2 in smem; within each 16-k group the 8 f16x2
// words are permuted (pair p -> word p<4 ? 2p : 2p-7) so the fragment pair
// (b0 = k{2s,2s+1}, b1 = k{2s+8,2s+9}) is one 8-byte LDS at word 8ks+2s.
// A fragments load directly from L2-resident g_agg as float2 + cvt, no smem.
// ---------------------------------------------------------------------------
__device__ __forceinline__ uint32_t packh(float hi, float lo) {
    uint32_t r;
    asm("cvt.rn.f16x2.f32 %0, %1, %2;" : "=r"(r) : "f"(hi), "f"(lo));
    return r;
}
__device__ __forceinline__ void mma16816h(float* c, uint32_t a0, uint32_t a1,
                                          uint32_t a2, uint32_t a3,
                                          uint32_t b0, uint32_t b1) {
    asm volatile(
        "mma.sync.aligned.m16n8k16.row.col.f32.f16.f16.f32 "
        "{%0,%1,%2,%3}, {%4,%5,%6,%7}, {%8,%9}, {%0,%1,%2,%3};"
        : "+f"(c[0]), "+f"(c[1]), "+f"(c[2]), "+f"(c[3])
        : "r"(a0), "r"(a1), "r"(a2), "r"(a3), "r"(b0), "r"(b1));
}

__global__ __launch_bounds__(256, 2) void gcn_mma_kernel(
    const float* __restrict__ W, const float* __restrict__ bias,
    float* __restrict__ out, int nrows) {
    __shared__ uint32_t Bs[DD * STRB];            // 36 KB

    const int t = threadIdx.x, wid = t >> 5, lane = t & 31;
    const int g = lane >> 2, s = lane & 3;
    const int warpM = (wid & 3) * 32;             // 4 warps over M (32 rows each)
    const int warpN = (wid >> 2) * 64;            // 2 warps over N (64 cols each)

    // ---- Stage W -> f16x2 smem with k-pair permutation ----
    #pragma unroll
    for (int i = 0; i < 32; i++) {
        int p = t + i * 256;                      // 0..8191 = n*64 + pw
        int n = p >> 6, pw = p & 63;              // pw = k-pair index
        float2 w = *reinterpret_cast<const float2*>(W + n * DD + pw * 2);
        int pp = pw & 7, G = pw >> 3;
        int j = G * 8 + ((pp < 4) ? 2 * pp : 2 * pp - 7);
        Bs[n * STRB + j] = packh(w.y, w.x);       // hi = odd k
    }

    // ---- A row pointers / predicates ----
    const int r0 = blockIdx.x * 128 + warpM + g;  // rows r0, +8, +16, +24
    const float* Ap = g_agg + (size_t)r0 * DD + 2 * s;
    bool pr[4];
    #pragma unroll
    for (int j = 0; j < 4; j++) pr[j] = (r0 + 8 * j) < nrows;
    const float2 zz = make_float2(0.f, 0.f);

    __syncthreads();

    float acc[2][8][4];
    #pragma unroll
    for (int mt = 0; mt < 2; mt++)
        #pragma unroll
        for (int nt = 0; nt < 8; nt++)
            #pragma unroll
            for (int c = 0; c < 4; c++) acc[mt][nt][c] = 0.f;

    const uint32_t* Bl = &Bs[(warpN + g) * STRB + 2 * s];

    #pragma unroll
    for (int ks = 0; ks < 8; ks++) {
        const int k0 = ks * 16;
        uint32_t A[2][4];
        #pragma unroll
        for (int mt = 0; mt < 2; mt++) {
            const float* a = Ap + (mt * 16) * DD + k0;
            float2 v00 = pr[mt * 2]     ? *reinterpret_cast<const float2*>(a)           : zz;
            float2 v01 = pr[mt * 2]     ? *reinterpret_cast<const float2*>(a + 8)       : zz;
            float2 v10 = pr[mt * 2 + 1] ? *reinterpret_cast<const float2*>(a + 8 * DD)     : zz;
            float2 v11 = pr[mt * 2 + 1] ? *reinterpret_cast<const float2*>(a + 8 * DD + 8) : zz;
            A[mt][0] = packh(v00.y, v00.x);       // row g,   k {2s,2s+1}
            A[mt][1] = packh(v10.y, v10.x);       // row g+8, k {2s,2s+1}
            A[mt][2] = packh(v01.y, v01.x);       // row g,   k {2s+8,2s+9}
            A[mt][3] = packh(v11.y, v11.x);       // row g+8, k {2s+8,2s+9}
        }
        #pragma unroll
        for (int nt = 0; nt < 8; nt++) {
            uint2 b = *reinterpret_cast<const uint2*>(Bl + nt * 8 * STRB + ks * 8);
            mma16816h(acc[0][nt], A[0][0], A[0][1], A[0][2], A[0][3], b.x, b.y);
            mma16816h(acc[1][nt], A[1][0], A[1][1], A[1][2], A[1][3], b.x, b.y);
        }
    }

    // ---- Epilogue: out[m][n] = acc * inv_deg[m] + bias[n] ----
    float inv[4];
    #pragma unroll
    for (int j = 0; j < 4; j++) {
        float dg = pr[j] ? g_deg[r0 + 8 * j] : 0.f;
        inv[j] = (dg > 0.f) ? (1.f / dg) : 0.f;
    }
    #pragma unroll
    for (int mt = 0; mt < 2; mt++) {
        #pragma unroll
        for (int nt = 0; nt < 8; nt++) {
            int n = warpN + nt * 8 + 2 * s;
            float2 bv = *reinterpret_cast<const float2*>(&bias[n]);
            int rA = r0 + mt * 16, rB = rA + 8;
            if (pr[mt * 2]) {
                float2 o = make_float2(acc[mt][nt][0] * inv[mt * 2] + bv.x,
                                       acc[mt][nt][1] * inv[mt * 2] + bv.y);
                *reinterpret_cast<float2*>(&out[(size_t)rA * DD + n]) = o;
            }
            if (pr[mt * 2 + 1]) {
                float2 o = make_float2(acc[mt][nt][2] * inv[mt * 2 + 1] + bv.x,
                                       acc[mt][nt][3] * inv[mt * 2 + 1] + bv.y);
                *reinterpret_cast<float2*>(&out[(size_t)rB * DD + n]) = o;
            }
        }
    }
}

extern "C" void kernel_launch(void* const* d_in, const int* in_sizes, int n_in,
                              void* d_out, int out_size) {
    const float* feature = (const float*)d_in[0];   // [100000,128] f32
    const float* W       = (const float*)d_in[1];   // [128,128]   f32
    const float* bias    = (const float*)d_in[2];   // [128]       f32
    const void*  src     = d_in[3];                 // [625000] int64/int32
    const void*  dst     = d_in[4];                 // [625000] int64/int32
    float*       out     = (float*)d_out;           // [100000,128] f32

    const int nE = in_sizes[3];
    const int nN = in_sizes[0] / DD;

    prep_kernel<<<(NN * DD / 4 + 255) / 256, 256>>>((const unsigned int*)src);

    long long scatter_threads = (long long)nE * 8;   // 8 lanes per edge
    scatter_kernel<<<(unsigned)((scatter_threads + 255) / 256), 256>>>(
        src, dst, (const float4*)feature, nE);

    gcn_mma_kernel<<<(nN + 127) / 128, 256>>>(W, bias, out, nN);
}

// round 6
// speedup vs baseline: 1.3769x; 1.1287x over previous
#include <cuda_runtime.h>
#include <cuda_fp16.h>
#include <cstdint>

#define NN 100000
#define DD 128
#define STRB 72      // 32-bit words per smem B row (72 mod 32 = 8 -> conflict-free)

// Scratch (static device globals — allocation-free at runtime)
__device__ float g_agg[NN * DD];   // 51.2 MB edge-sum accumulator
__device__ float g_deg[NN];        // in-degree (float)
__device__ int   g_is64;           // 1 if src/dst are int64

// ---------------------------------------------------------------------------
// Index dtype detect, one warp: int64 values < 2^31 have all-zero odd 32-bit
// words; int32 node ids over 512 samples cannot. Lane-parallel + warp OR.
// ---------------------------------------------------------------------------
__global__ void detect_kernel(const unsigned int* __restrict__ src) {
    unsigned int acc = 0;
    int lane = threadIdx.x;
    #pragma unroll
    for (int j = 0; j < 16; j++) acc |= src[2 * (lane * 16 + j) + 1];
    acc = __reduce_or_sync(0xFFFFFFFFu, acc);
    if (lane == 0) g_is64 = (acc == 0u) ? 1 : 0;
}

// ---------------------------------------------------------------------------
// Edge scatter: 4 edges per warp, 8 lanes per edge, 4 float4 per lane.
// At the LTS cap (~10 TB/s effective L2) — unchanged.
// ---------------------------------------------------------------------------
__global__ void scatter_kernel(const void* __restrict__ srcv,
                               const void* __restrict__ dstv,
                               const float4* __restrict__ feat4, int nE) {
    int gid = blockIdx.x * blockDim.x + threadIdx.x;
    int warp = gid >> 5, lane = gid & 31;
    int e = warp * 4 + (lane >> 3);
    if (e >= nE) return;
    int li = lane & 7;

    long long s, d;
    if (g_is64) {
        s = reinterpret_cast<const long long*>(srcv)[e];
        d = reinterpret_cast<const long long*>(dstv)[e];
    } else {
        s = reinterpret_cast<const int*>(srcv)[e];
        d = reinterpret_cast<const int*>(dstv)[e];
    }

    float4 v[4];
    #pragma unroll
    for (int j = 0; j < 4; j++) v[j] = feat4[s * 32 + li + j * 8];
    #pragma unroll
    for (int j = 0; j < 4; j++) {
        float* p = &g_agg[d * DD + (li + j * 8) * 4];
        asm volatile("red.global.add.v4.f32 [%0], {%1,%2,%3,%4};"
                     :: "l"(p), "f"(v[j].x), "f"(v[j].y), "f"(v[j].z), "f"(v[j].w)
                     : "memory");
    }
    if (li == 0) atomicAdd(&g_deg[d], 1.0f);
}

// ---------------------------------------------------------------------------
// Single-pass fp16 GEMM via mma.sync.m16n8k16.f32.f16.f16.f32:
//   out[m] = (agg[m] * inv_deg[m]) @ W^T + b
// fp16 has 11 significand bits -> ~3e-4 output rel err (fp32 accumulate).
// B = W[n][k] converted to f16x2 in smem; within each 16-k group the 8 f16x2
// words are permuted (pair p -> word p<4 ? 2p : 2p-7) so the fragment pair
// (b0 = k{2s,2s+1}, b1 = k{2s+8,2s+9}) is one 8-byte LDS at word 8ks+2s.
// A fragments load directly from L2-resident g_agg as float2 + cvt, no smem.
// ---------------------------------------------------------------------------
__device__ __forceinline__ uint32_t packh(float hi, float lo) {
    uint32_t r;
    asm("cvt.rn.f16x2.f32 %0, %1, %2;" : "=r"(r) : "f"(hi), "f"(lo));
    return r;
}
__device__ __forceinline__ void mma16816h(float* c, uint32_t a0, uint32_t a1,
                                          uint32_t a2, uint32_t a3,
                                          uint32_t b0, uint32_t b1) {
    asm volatile(
        "mma.sync.aligned.m16n8k16.row.col.f32.f16.f16.f32 "
        "{%0,%1,%2,%3}, {%4,%5,%6,%7}, {%8,%9}, {%0,%1,%2,%3};"
        : "+f"(c[0]), "+f"(c[1]), "+f"(c[2]), "+f"(c[3])
        : "r"(a0), "r"(a1), "r"(a2), "r"(a3), "r"(b0), "r"(b1));
}

__global__ __launch_bounds__(256, 2) void gcn_mma_kernel(
    const float* __restrict__ W, const float* __restrict__ bias,
    float* __restrict__ out, int nrows) {
    __shared__ uint32_t Bs[DD * STRB];            // 36 KB

    const int t = threadIdx.x, wid = t >> 5, lane = t & 31;
    const int g = lane >> 2, s = lane & 3;
    const int warpM = (wid & 3) * 32;             // 4 warps over M (32 rows each)
    const int warpN = (wid >> 2) * 64;            // 2 warps over N (64 cols each)

    // ---- Stage W -> f16x2 smem with k-pair permutation ----
    #pragma unroll
    for (int i = 0; i < 32; i++) {
        int p = t + i * 256;                      // 0..8191 = n*64 + pw
        int n = p >> 6, pw = p & 63;              // pw = k-pair index
        float2 w = *reinterpret_cast<const float2*>(W + n * DD + pw * 2);
        int pp = pw & 7, G = pw >> 3;
        int j = G * 8 + ((pp < 4) ? 2 * pp : 2 * pp - 7);
        Bs[n * STRB + j] = packh(w.y, w.x);       // hi = odd k
    }

    // ---- A row pointers / predicates ----
    const int r0 = blockIdx.x * 128 + warpM + g;  // rows r0, +8, +16, +24
    const float* Ap = g_agg + (size_t)r0 * DD + 2 * s;
    bool pr[4];
    #pragma unroll
    for (int j = 0; j < 4; j++) pr[j] = (r0 + 8 * j) < nrows;
    const float2 zz = make_float2(0.f, 0.f);

    __syncthreads();

    float acc[2][8][4];
    #pragma unroll
    for (int mt = 0; mt < 2; mt++)
        #pragma unroll
        for (int nt = 0; nt < 8; nt++)
            #pragma unroll
            for (int c = 0; c < 4; c++) acc[mt][nt][c] = 0.f;

    const uint32_t* Bl = &Bs[(warpN + g) * STRB + 2 * s];

    #pragma unroll
    for (int ks = 0; ks < 8; ks++) {
        const int k0 = ks * 16;
        uint32_t A[2][4];
        #pragma unroll
        for (int mt = 0; mt < 2; mt++) {
            const float* a = Ap + (mt * 16) * DD + k0;
            float2 v00 = pr[mt * 2]     ? *reinterpret_cast<const float2*>(a)           : zz;
            float2 v01 = pr[mt * 2]     ? *reinterpret_cast<const float2*>(a + 8)       : zz;
            float2 v10 = pr[mt * 2 + 1] ? *reinterpret_cast<const float2*>(a + 8 * DD)     : zz;
            float2 v11 = pr[mt * 2 + 1] ? *reinterpret_cast<const float2*>(a + 8 * DD + 8) : zz;
            A[mt][0] = packh(v00.y, v00.x);       // row g,   k {2s,2s+1}
            A[mt][1] = packh(v10.y, v10.x);       // row g+8, k {2s,2s+1}
            A[mt][2] = packh(v01.y, v01.x);       // row g,   k {2s+8,2s+9}
            A[mt][3] = packh(v11.y, v11.x);       // row g+8, k {2s+8,2s+9}
        }
        #pragma unroll
        for (int nt = 0; nt < 8; nt++) {
            uint2 b = *reinterpret_cast<const uint2*>(Bl + nt * 8 * STRB + ks * 8);
            mma16816h(acc[0][nt], A[0][0], A[0][1], A[0][2], A[0][3], b.x, b.y);
            mma16816h(acc[1][nt], A[1][0], A[1][1], A[1][2], A[1][3], b.x, b.y);
        }
    }

    // ---- Epilogue: out[m][n] = acc * inv_deg[m] + bias[n] ----
    float inv[4];
    #pragma unroll
    for (int j = 0; j < 4; j++) {
        float dg = pr[j] ? g_deg[r0 + 8 * j] : 0.f;
        inv[j] = (dg > 0.f) ? (1.f / dg) : 0.f;
    }
    #pragma unroll
    for (int mt = 0; mt < 2; mt++) {
        #pragma unroll
        for (int nt = 0; nt < 8; nt++) {
            int n = warpN + nt * 8 + 2 * s;
            float2 bv = *reinterpret_cast<const float2*>(&bias[n]);
            int rA = r0 + mt * 16, rB = rA + 8;
            if (pr[mt * 2]) {
                float2 o = make_float2(acc[mt][nt][0] * inv[mt * 2] + bv.x,
                                       acc[mt][nt][1] * inv[mt * 2] + bv.y);
                *reinterpret_cast<float2*>(&out[(size_t)rA * DD + n]) = o;
            }
            if (pr[mt * 2 + 1]) {
                float2 o = make_float2(acc[mt][nt][2] * inv[mt * 2 + 1] + bv.x,
                                       acc[mt][nt][3] * inv[mt * 2 + 1] + bv.y);
                *reinterpret_cast<float2*>(&out[(size_t)rB * DD + n]) = o;
            }
        }
    }
}

extern "C" void kernel_launch(void* const* d_in, const int* in_sizes, int n_in,
                              void* d_out, int out_size) {
    const float* feature = (const float*)d_in[0];   // [100000,128] f32
    const float* W       = (const float*)d_in[1];   // [128,128]   f32
    const float* bias    = (const float*)d_in[2];   // [128]       f32
    const void*  src     = d_in[3];                 // [625000] int64/int32
    const void*  dst     = d_in[4];                 // [625000] int64/int32
    float*       out     = (float*)d_out;           // [100000,128] f32

    const int nE = in_sizes[3];
    const int nN = in_sizes[0] / DD;

    // Zero scratch via graph memset nodes (no allocation; capture-legal).
    void* agg_ptr = nullptr; void* deg_ptr = nullptr;
    cudaGetSymbolAddress(&agg_ptr, g_agg);
    cudaGetSymbolAddress(&deg_ptr, g_deg);
    cudaMemsetAsync(agg_ptr, 0, sizeof(float) * NN * DD, 0);
    cudaMemsetAsync(deg_ptr, 0, sizeof(float) * NN, 0);

    detect_kernel<<<1, 32>>>((const unsigned int*)src);

    long long scatter_threads = (long long)nE * 8;   // 8 lanes per edge
    scatter_kernel<<<(unsigned)((scatter_threads + 255) / 256), 256>>>(
        src, dst, (const float4*)feature, nE);

    gcn_mma_kernel<<<(nN + 127) / 128, 256>>>(W, bias, out, nN);
}

// round 7
// speedup vs baseline: 1.4259x; 1.0356x over previous
#include <cuda_runtime.h>
#include <cuda_fp16.h>
#include <cstdint>

#define NN 100000
#define DD 128
#define STRB 72      // 32-bit words per smem B row (72 mod 32 = 8 -> conflict-free)

// Scratch (static device globals — allocation-free at runtime)
__device__ float g_agg[NN * DD];   // 51.2 MB edge-sum accumulator
__device__ float g_deg[NN];        // in-degree (float)

// ---------------------------------------------------------------------------
// Edge scatter: 4 edges per warp, 8 lanes per edge, 4 float4 per lane.
// Index dtype detected in-warp: odd 32-bit words of int64 values < 2^31 are
// all zero; 32 random int32 node ids cannot all be zero (p ~ 1e-160).
// ---------------------------------------------------------------------------
__global__ void scatter_kernel(const void* __restrict__ srcv,
                               const void* __restrict__ dstv,
                               const float4* __restrict__ feat4, int nE) {
    int gid = blockIdx.x * blockDim.x + threadIdx.x;
    int warp = gid >> 5, lane = gid & 31;

    // per-warp dtype probe (before any early exit — full warp participates)
    unsigned int probe = reinterpret_cast<const unsigned int*>(srcv)[2 * lane + 1];
    bool is64 = (__reduce_or_sync(0xFFFFFFFFu, probe) == 0u);

    int e = warp * 4 + (lane >> 3);
    if (e >= nE) return;
    int li = lane & 7;

    long long s, d;
    if (is64) {
        s = reinterpret_cast<const long long*>(srcv)[e];
        d = reinterpret_cast<const long long*>(dstv)[e];
    } else {
        s = reinterpret_cast<const int*>(srcv)[e];
        d = reinterpret_cast<const int*>(dstv)[e];
    }

    float4 v[4];
    #pragma unroll
    for (int j = 0; j < 4; j++) v[j] = feat4[s * 32 + li + j * 8];
    #pragma unroll
    for (int j = 0; j < 4; j++) {
        float* p = &g_agg[d * DD + (li + j * 8) * 4];
        asm volatile("red.global.add.v4.f32 [%0], {%1,%2,%3,%4};"
                     :: "l"(p), "f"(v[j].x), "f"(v[j].y), "f"(v[j].z), "f"(v[j].w)
                     : "memory");
    }
    if (li == 0) atomicAdd(&g_deg[d], 1.0f);
}

// ---------------------------------------------------------------------------
// Single-pass fp16 GEMM via mma.sync.m16n8k16.f32.f16.f16.f32:
//   out[m] = (agg[m] * inv_deg[m]) @ W^T + b
// B = W[n][k] as f16x2 in smem with k-pair permutation so each fragment pair
// is one conflict-free LDS.64. A fragments stream from L2-resident g_agg,
// software-pipelined one k-step ahead so LDG latency hides under HMMA issue.
// ---------------------------------------------------------------------------
__device__ __forceinline__ uint32_t packh(float hi, float lo) {
    uint32_t r;
    asm("cvt.rn.f16x2.f32 %0, %1, %2;" : "=r"(r) : "f"(hi), "f"(lo));
    return r;
}
__device__ __forceinline__ void mma16816h(float* c, uint32_t a0, uint32_t a1,
                                          uint32_t a2, uint32_t a3,
                                          uint32_t b0, uint32_t b1) {
    asm volatile(
        "mma.sync.aligned.m16n8k16.row.col.f32.f16.f16.f32 "
        "{%0,%1,%2,%3}, {%4,%5,%6,%7}, {%8,%9}, {%0,%1,%2,%3};"
        : "+f"(c[0]), "+f"(c[1]), "+f"(c[2]), "+f"(c[3])
        : "r"(a0), "r"(a1), "r"(a2), "r"(a3), "r"(b0), "r"(b1));
}

__global__ __launch_bounds__(256, 2) void gcn_mma_kernel(
    const float* __restrict__ W, const float* __restrict__ bias,
    float* __restrict__ out, int nrows) {
    __shared__ uint32_t Bs[DD * STRB];            // 36 KB

    const int t = threadIdx.x, wid = t >> 5, lane = t & 31;
    const int g = lane >> 2, s = lane & 3;
    const int warpM = (wid & 3) * 32;             // 4 warps over M (32 rows each)
    const int warpN = (wid >> 2) * 64;            // 2 warps over N (64 cols each)

    // ---- Stage W -> f16x2 smem with k-pair permutation ----
    #pragma unroll
    for (int i = 0; i < 32; i++) {
        int p = t + i * 256;                      // 0..8191 = n*64 + pw
        int n = p >> 6, pw = p & 63;              // pw = k-pair index
        float2 w = *reinterpret_cast<const float2*>(W + n * DD + pw * 2);
        int pp = pw & 7, G = pw >> 3;
        int j = G * 8 + ((pp < 4) ? 2 * pp : 2 * pp - 7);
        Bs[n * STRB + j] = packh(w.y, w.x);       // hi = odd k
    }

    // ---- A row pointers / predicates ----
    const int r0 = blockIdx.x * 128 + warpM + g;  // rows r0, +8, +16, +24
    const float* Ap = g_agg + (size_t)r0 * DD + 2 * s;
    bool pr[4];
    #pragma unroll
    for (int j = 0; j < 4; j++) pr[j] = (r0 + 8 * j) < nrows;
    const float2 zz = make_float2(0.f, 0.f);

    // ---- Prologue: load k-step 0 raw float2s ----
    float2 V[2][4];
    #pragma unroll
    for (int mt = 0; mt < 2; mt++) {
        const float* a = Ap + (mt * 16) * DD;
        V[mt][0] = pr[mt * 2]     ? *reinterpret_cast<const float2*>(a)            : zz;
        V[mt][1] = pr[mt * 2 + 1] ? *reinterpret_cast<const float2*>(a + 8 * DD)      : zz;
        V[mt][2] = pr[mt * 2]     ? *reinterpret_cast<const float2*>(a + 8)        : zz;
        V[mt][3] = pr[mt * 2 + 1] ? *reinterpret_cast<const float2*>(a + 8 * DD + 8)  : zz;
    }

    __syncthreads();

    float acc[2][8][4];
    #pragma unroll
    for (int mt = 0; mt < 2; mt++)
        #pragma unroll
        for (int nt = 0; nt < 8; nt++)
            #pragma unroll
            for (int c = 0; c < 4; c++) acc[mt][nt][c] = 0.f;

    const uint32_t* Bl = &Bs[(warpN + g) * STRB + 2 * s];

    #pragma unroll
    for (int ks = 0; ks < 8; ks++) {
        // convert current stage to fragments
        uint32_t A[2][4];
        #pragma unroll
        for (int mt = 0; mt < 2; mt++) {
            A[mt][0] = packh(V[mt][0].y, V[mt][0].x);   // row g,   k {2s,2s+1}
            A[mt][1] = packh(V[mt][1].y, V[mt][1].x);   // row g+8, k {2s,2s+1}
            A[mt][2] = packh(V[mt][2].y, V[mt][2].x);   // row g,   k {2s+8,2s+9}
            A[mt][3] = packh(V[mt][3].y, V[mt][3].x);   // row g+8, k {2s+8,2s+9}
        }
        // prefetch next stage (LDGs issue before the HMMA burst)
        if (ks < 7) {
            const int k1 = (ks + 1) * 16;
            #pragma unroll
            for (int mt = 0; mt < 2; mt++) {
                const float* a = Ap + (mt * 16) * DD + k1;
                V[mt][0] = pr[mt * 2]     ? *reinterpret_cast<const float2*>(a)            : zz;
                V[mt][1] = pr[mt * 2 + 1] ? *reinterpret_cast<const float2*>(a + 8 * DD)      : zz;
                V[mt][2] = pr[mt * 2]     ? *reinterpret_cast<const float2*>(a + 8)        : zz;
                V[mt][3] = pr[mt * 2 + 1] ? *reinterpret_cast<const float2*>(a + 8 * DD + 8)  : zz;
            }
        }
        #pragma unroll
        for (int nt = 0; nt < 8; nt++) {
            uint2 b = *reinterpret_cast<const uint2*>(Bl + nt * 8 * STRB + ks * 8);
            mma16816h(acc[0][nt], A[0][0], A[0][1], A[0][2], A[0][3], b.x, b.y);
            mma16816h(acc[1][nt], A[1][0], A[1][1], A[1][2], A[1][3], b.x, b.y);
        }
    }

    // ---- Epilogue: out[m][n] = acc * inv_deg[m] + bias[n] ----
    float inv[4];
    #pragma unroll
    for (int j = 0; j < 4; j++) {
        float dg = pr[j] ? g_deg[r0 + 8 * j] : 0.f;
        inv[j] = (dg > 0.f) ? (1.f / dg) : 0.f;
    }
    #pragma unroll
    for (int mt = 0; mt < 2; mt++) {
        #pragma unroll
        for (int nt = 0; nt < 8; nt++) {
            int n = warpN + nt * 8 + 2 * s;
            float2 bv = *reinterpret_cast<const float2*>(&bias[n]);
            int rA = r0 + mt * 16, rB = rA + 8;
            if (pr[mt * 2]) {
                float2 o = make_float2(acc[mt][nt][0] * inv[mt * 2] + bv.x,
                                       acc[mt][nt][1] * inv[mt * 2] + bv.y);
                *reinterpret_cast<float2*>(&out[(size_t)rA * DD + n]) = o;
            }
            if (pr[mt * 2 + 1]) {
                float2 o = make_float2(acc[mt][nt][2] * inv[mt * 2 + 1] + bv.x,
                                       acc[mt][nt][3] * inv[mt * 2 + 1] + bv.y);
                *reinterpret_cast<float2*>(&out[(size_t)rB * DD + n]) = o;
            }
        }
    }
}

extern "C" void kernel_launch(void* const* d_in, const int* in_sizes, int n_in,
                              void* d_out, int out_size) {
    const float* feature = (const float*)d_in[0];   // [100000,128] f32
    const float* W       = (const float*)d_in[1];   // [128,128]   f32
    const float* bias    = (const float*)d_in[2];   // [128]       f32
    const void*  src     = d_in[3];                 // [625000] int64/int32
    const void*  dst     = d_in[4];                 // [625000] int64/int32
    float*       out     = (float*)d_out;           // [100000,128] f32

    const int nE = in_sizes[3];
    const int nN = in_sizes[0] / DD;

    // Zero scratch via graph memset nodes (no allocation; capture-legal).
    void* agg_ptr = nullptr; void* deg_ptr = nullptr;
    cudaGetSymbolAddress(&agg_ptr, g_agg);
    cudaGetSymbolAddress(&deg_ptr, g_deg);
    cudaMemsetAsync(agg_ptr, 0, sizeof(float) * NN * DD, 0);
    cudaMemsetAsync(deg_ptr, 0, sizeof(float) * NN, 0);

    long long scatter_threads = (long long)nE * 8;   // 8 lanes per edge
    scatter_kernel<<<(unsigned)((scatter_threads + 255) / 256), 256>>>(
        src, dst, (const float4*)feature, nE);

    gcn_mma_kernel<<<(nN + 127) / 128, 256>>>(W, bias, out, nN);
}

// round 9
// speedup vs baseline: 1.4542x; 1.0199x over previous
#include <cuda_runtime.h>
#include <cuda_fp16.h>
#include <cstdint>

#define NN 100000
#define DD 128
#define STRB 72      // 32-bit words per smem B row (72 mod 32 = 8 -> conflict-free)
#define ASTR 132     // f32 words per smem A row (528 B, 16B-aligned, low-conflict)
#define SM_B_BYTES (DD * STRB * 4)            // 36864
#define SM_A_BYTES (DD * ASTR * 4)            // 67584
#define SM_TOTAL   (SM_B_BYTES + SM_A_BYTES)  // 104448

// Scratch (static device globals — allocation-free at runtime)
__device__ float g_agg[NN * DD];   // 51.2 MB edge-sum accumulator
__device__ float g_deg[NN];        // in-degree (float)

// ---------------------------------------------------------------------------
// Edge scatter: 4 edges per warp, 8 lanes per edge, 4 float4 per lane.
// Index dtype detected in-warp: odd 32-bit words of int64 values < 2^31 are
// all zero; 32 random int32 node ids cannot all be zero.
// ---------------------------------------------------------------------------
__global__ void scatter_kernel(const void* __restrict__ srcv,
                               const void* __restrict__ dstv,
                               const float4* __restrict__ feat4, int nE) {
    int gid = blockIdx.x * blockDim.x + threadIdx.x;
    int warp = gid >> 5, lane = gid & 31;

    unsigned int probe = reinterpret_cast<const unsigned int*>(srcv)[2 * lane + 1];
    bool is64 = (__reduce_or_sync(0xFFFFFFFFu, probe) == 0u);

    int e = warp * 4 + (lane >> 3);
    if (e >= nE) return;
    int li = lane & 7;

    long long s, d;
    if (is64) {
        s = reinterpret_cast<const long long*>(srcv)[e];
        d = reinterpret_cast<const long long*>(dstv)[e];
    } else {
        s = reinterpret_cast<const int*>(srcv)[e];
        d = reinterpret_cast<const int*>(dstv)[e];
    }

    float4 v[4];
    #pragma unroll
    for (int j = 0; j < 4; j++) v[j] = feat4[s * 32 + li + j * 8];
    #pragma unroll
    for (int j = 0; j < 4; j++) {
        float* p = &g_agg[d * DD + (li + j * 8) * 4];
        asm volatile("red.global.add.v4.f32 [%0], {%1,%2,%3,%4};"
                     :: "l"(p), "f"(v[j].x), "f"(v[j].y), "f"(v[j].z), "f"(v[j].w)
                     : "memory");
    }
    if (li == 0) atomicAdd(&g_deg[d], 1.0f);
}

// ---------------------------------------------------------------------------
// Single-pass fp16 GEMM via mma.sync.m16n8k16.f32.f16.f16.f32:
//   out[m] = (agg[m] * inv_deg[m]) @ W^T + b
// Full A tile (128x128 f32) staged via one cp.async burst (max MLP); B = W
// staged as f16x2 with k-pair permutation (fragment pair = one LDS.64).
// Mainloop touches only smem -> latency-tolerant at 2 CTAs/SM.
// ---------------------------------------------------------------------------
__device__ __forceinline__ uint32_t smem_u32(const void* p) {
    uint32_t a;
    asm("{ .reg .u64 t; cvta.to.shared.u64 t, %1; cvt.u32.u64 %0, t; }"
        : "=r"(a) : "l"(p));
    return a;
}
__device__ __forceinline__ uint32_t packh(float hi, float lo) {
    uint32_t r;
    asm("cvt.rn.f16x2.f32 %0, %1, %2;" : "=r"(r) : "f"(hi), "f"(lo));
    return r;
}
__device__ __forceinline__ void mma16816h(float* c, uint32_t a0, uint32_t a1,
                                          uint32_t a2, uint32_t a3,
                                          uint32_t b0, uint32_t b1) {
    asm volatile(
        "mma.sync.aligned.m16n8k16.row.col.f32.f16.f16.f32 "
        "{%0,%1,%2,%3}, {%4,%5,%6,%7}, {%8,%9}, {%0,%1,%2,%3};"
        : "+f"(c[0]), "+f"(c[1]), "+f"(c[2]), "+f"(c[3])
        : "r"(a0), "r"(a1), "r"(a2), "r"(a3), "r"(b0), "r"(b1));
}

__global__ __launch_bounds__(256, 2) void gcn_mma_kernel(
    const float* __restrict__ W, const float* __restrict__ bias,
    float* __restrict__ out, int nrows) {
    extern __shared__ char smem[];
    uint32_t* Bs = reinterpret_cast<uint32_t*>(smem);
    float*    As = reinterpret_cast<float*>(smem + SM_B_BYTES);

    const int t = threadIdx.x, wid = t >> 5, lane = t & 31;
    const int g = lane >> 2, s = lane & 3;
    const int warpM = (wid & 3) * 32;             // 4 warps over M (32 rows each)
    const int warpN = (wid >> 2) * 64;            // 2 warps over N (64 cols each)
    const int row0 = blockIdx.x * 128;

    // ---- Issue full A tile via cp.async (16 x 16B per thread) ----
    {
        const uint32_t abase = smem_u32(As);
        #pragma unroll
        for (int i = 0; i < 16; i++) {
            int c = t + i * 256;                  // chunk: row = c>>5, part = c&31
            int row = c >> 5, part = c & 31;
            bool ok = (row0 + row) < nrows;
            // clamp src for OOB rows (src-size=0 -> zero-fill, no read)
            const float* gsrc = g_agg + (size_t)(ok ? row0 + row : row0) * DD + part * 4;
            uint32_t sdst = abase + (row * ASTR + part * 4) * 4;
            int sz = ok ? 16 : 0;
            asm volatile("cp.async.cg.shared.global [%0], [%1], 16, %2;"
                         :: "r"(sdst), "l"(gsrc), "r"(sz) : "memory");
        }
        asm volatile("cp.async.commit_group;" ::: "memory");
    }

    // ---- Stage W -> f16x2 smem (overlaps with A copies in flight) ----
    #pragma unroll
    for (int i = 0; i < 32; i++) {
        int p = t + i * 256;                      // 0..8191 = n*64 + pw
        int n = p >> 6, pw = p & 63;              // pw = k-pair index
        float2 w = *reinterpret_cast<const float2*>(W + n * DD + pw * 2);
        int pp = pw & 7, G = pw >> 3;
        int j = G * 8 + ((pp < 4) ? 2 * pp : 2 * pp - 7);
        Bs[n * STRB + j] = packh(w.y, w.x);       // hi = odd k
    }

    const int r0 = row0 + warpM + g;              // rows r0, +8, +16, +24
    bool pr[4];
    #pragma unroll
    for (int j = 0; j < 4; j++) pr[j] = (r0 + 8 * j) < nrows;

    float acc[2][8][4];
    #pragma unroll
    for (int mt = 0; mt < 2; mt++)
        #pragma unroll
        for (int nt = 0; nt < 8; nt++)
            #pragma unroll
            for (int c = 0; c < 4; c++) acc[mt][nt][c] = 0.f;

    asm volatile("cp.async.wait_group 0;" ::: "memory");
    __syncthreads();

    const uint32_t* Bl = &Bs[(warpN + g) * STRB + 2 * s];
    const float*    Al = As + (warpM + g) * ASTR + 2 * s;

    #pragma unroll
    for (int ks = 0; ks < 8; ks++) {
        const int k0 = ks * 16;
        uint32_t A[2][4];
        #pragma unroll
        for (int mt = 0; mt < 2; mt++) {
            const float* a = Al + (mt * 16) * ASTR + k0;
            float2 v00 = *reinterpret_cast<const float2*>(a);
            float2 v10 = *reinterpret_cast<const float2*>(a + 8 * ASTR);
            float2 v01 = *reinterpret_cast<const float2*>(a + 8);
            float2 v11 = *reinterpret_cast<const float2*>(a + 8 * ASTR + 8);
            A[mt][0] = packh(v00.y, v00.x);       // row g,   k {2s,2s+1}
            A[mt][1] = packh(v10.y, v10.x);       // row g+8, k {2s,2s+1}
            A[mt][2] = packh(v01.y, v01.x);       // row g,   k {2s+8,2s+9}
            A[mt][3] = packh(v11.y, v11.x);       // row g+8, k {2s+8,2s+9}
        }
        #pragma unroll
        for (int nt = 0; nt < 8; nt++) {
            uint2 b = *reinterpret_cast<const uint2*>(Bl + nt * 8 * STRB + ks * 8);
            mma16816h(acc[0][nt], A[0][0], A[0][1], A[0][2], A[0][3], b.x, b.y);
            mma16816h(acc[1][nt], A[1][0], A[1][1], A[1][2], A[1][3], b.x, b.y);
        }
    }

    // ---- Epilogue: out[m][n] = acc * inv_deg[m] + bias[n] ----
    float inv[4];
    #pragma unroll
    for (int j = 0; j < 4; j++) {
        float dg = pr[j] ? g_deg[r0 + 8 * j] : 0.f;
        inv[j] = (dg > 0.f) ? (1.f / dg) : 0.f;
    }
    #pragma unroll
    for (int mt = 0; mt < 2; mt++) {
        #pragma unroll
        for (int nt = 0; nt < 8; nt++) {
            int n = warpN + nt * 8 + 2 * s;
            float2 bv = *reinterpret_cast<const float2*>(&bias[n]);
            int rA = r0 + mt * 16, rB = rA + 8;
            if (pr[mt * 2]) {
                float2 o = make_float2(acc[mt][nt][0] * inv[mt * 2] + bv.x,
                                       acc[mt][nt][1] * inv[mt * 2] + bv.y);
                *reinterpret_cast<float2*>(&out[(size_t)rA * DD + n]) = o;
            }
            if (pr[mt * 2 + 1]) {
                float2 o = make_float2(acc[mt][nt][2] * inv[mt * 2 + 1] + bv.x,
                                       acc[mt][nt][3] * inv[mt * 2 + 1] + bv.y);
                *reinterpret_cast<float2*>(&out[(size_t)rB * DD + n]) = o;
            }
        }
    }
}

extern "C" void kernel_launch(void* const* d_in, const int* in_sizes, int n_in,
                              void* d_out, int out_size) {
    const float* feature = (const float*)d_in[0];   // [100000,128] f32
    const float* W       = (const float*)d_in[1];   // [128,128]   f32
    const float* bias    = (const float*)d_in[2];   // [128]       f32
    const void*  src     = d_in[3];                 // [625000] int64/int32
    const void*  dst     = d_in[4];                 // [625000] int64/int32
    float*       out     = (float*)d_out;           // [100000,128] f32

    const int nE = in_sizes[3];
    const int nN = in_sizes[0] / DD;

    // Zero scratch via graph memset nodes (no allocation; capture-legal).
    void* agg_ptr = nullptr; void* deg_ptr = nullptr;
    cudaGetSymbolAddress(&agg_ptr, g_agg);
    cudaGetSymbolAddress(&deg_ptr, g_deg);
    cudaMemsetAsync(agg_ptr, 0, sizeof(float) * NN * DD, 0);
    cudaMemsetAsync(deg_ptr, 0, sizeof(float) * NN, 0);

    long long scatter_threads = (long long)nE * 8;   // 8 lanes per edge
    scatter_kernel<<<(unsigned)((scatter_threads + 255) / 256), 256>>>(
        src, dst, (const float4*)feature, nE);

    cudaFuncSetAttribute(gcn_mma_kernel,
                         cudaFuncAttributeMaxDynamicSharedMemorySize, SM_TOTAL);
    gcn_mma_kernel<<<(nN + 127) / 128, 256, SM_TOTAL>>>(W, bias, out, nN);
}